// round 3
// baseline (speedup 1.0000x reference)
#include <cuda_runtime.h>
#include <cuda_bf16.h>

// Problem constants (from reference): IN=4, H=30, OUT=1, N_UNIT=100, B=262144
#define NU   100
#define HH   30
#define ROWS 256   // rows per block == threads per block

// Scratch computed by setup kernel (no allocations allowed)
__device__ float g_cum[NU];    // exclusive cumulative Pmax of cheaper units, per ORIGINAL unit index
__device__ float g_sumPd;      // sum(Pd)

// ---------------------------------------------------------------------------
// Setup: replicate stable argsort(Cost) merit order.
// For original unit j: cum_prev_orig[j] = sum_k Pmax[k] over k with
// (Cost[k] < Cost[j]) || (Cost[k] == Cost[j] && k < j)   [stable-sort tie rule]
// ---------------------------------------------------------------------------
__global__ void setup_kernel(const float* __restrict__ Cost,
                             const float* __restrict__ Pmax,
                             const float* __restrict__ Pd) {
    __shared__ float sc[NU], sp[NU];
    int j = threadIdx.x;
    if (j < NU) { sc[j] = Cost[j]; sp[j] = Pmax[j]; }
    __syncthreads();
    if (j < NU) {
        float cj = sc[j];
        float cum = 0.0f;
        #pragma unroll 4
        for (int k = 0; k < NU; k++) {
            float ck = sc[k];
            bool cheaper = (ck < cj) || (ck == cj && k < j);
            if (cheaper) cum += sp[k];
        }
        g_cum[j] = cum;
    }
    if (j == 0) {
        float s = 0.0f;
        for (int k = 0; k < NU; k++) s += Pd[k];
        g_sumPd = s;
    }
}

// ---------------------------------------------------------------------------
// Main: MLP + dispatch. One thread per row for the MLP; whole block does
// coalesced float4 stores of the [ROWS, 100] output tile.
// ---------------------------------------------------------------------------
__global__ __launch_bounds__(ROWS)
void mlp_dispatch_kernel(const float4* __restrict__ x,        // [B,4] as float4
                         const float*  __restrict__ W1,       // [4,30]
                         const float*  __restrict__ b1,       // [30]
                         const float*  __restrict__ W2,       // [30,30]
                         const float*  __restrict__ b2,       // [30]
                         const float*  __restrict__ W3,       // [30,1]
                         const float*  __restrict__ b3,       // [1]
                         const float*  __restrict__ Pmax,     // [100]
                         const float*  __restrict__ wcap,     // [1]
                         float*        __restrict__ out)      // [B,100]
{
    __shared__ alignas(16) float sW1[4 * HH];
    __shared__ alignas(16) float sb1[HH];
    __shared__ alignas(16) float sW2[HH * HH];
    __shared__ alignas(16) float sb2[HH];
    __shared__ alignas(16) float sW3[HH];
    __shared__ alignas(16) float sCum[NU];
    __shared__ alignas(16) float sPmax[NU];
    __shared__ alignas(16) float sTd[ROWS];
    __shared__ float sB3, sWc, sSum;

    const int tid = threadIdx.x;

    // Cooperative staging of all parameters into shared
    for (int i = tid; i < 4 * HH;  i += ROWS) sW1[i] = W1[i];
    for (int i = tid; i < HH * HH; i += ROWS) sW2[i] = W2[i];
    if (tid < HH) { sb1[tid] = b1[tid]; sb2[tid] = b2[tid]; sW3[tid] = W3[tid]; }
    if (tid < NU) { sCum[tid] = g_cum[tid]; sPmax[tid] = Pmax[tid]; }
    if (tid == 0) { sB3 = b3[0]; sWc = wcap[0]; sSum = g_sumPd; }
    __syncthreads();

    // ---- MLP for this thread's row ----
    const long row = (long)blockIdx.x * ROWS + tid;
    const float4 xv = x[row];

    float h1[HH];
    #pragma unroll
    for (int k = 0; k < HH; k++) {
        float a = sb1[k];
        a = fmaf(xv.x, sW1[0 * HH + k], a);
        a = fmaf(xv.y, sW1[1 * HH + k], a);
        a = fmaf(xv.z, sW1[2 * HH + k], a);
        a = fmaf(xv.w, sW1[3 * HH + k], a);
        h1[k] = fmaxf(a, 0.0f);
    }

    float h2[HH];
    #pragma unroll
    for (int k = 0; k < HH; k++) {
        float a = sb2[k];
        #pragma unroll
        for (int i = 0; i < HH; i++)
            a = fmaf(h1[i], sW2[i * HH + k], a);
        h2[k] = fmaxf(a, 0.0f);
    }

    float y = sB3;
    #pragma unroll
    for (int i = 0; i < HH; i++)
        y = fmaf(h2[i], sW3[i], y);

    sTd[tid] = sSum - sWc * y;   // residual demand for this row
    __syncthreads();

    // ---- Coalesced tile store: ROWS rows x 100 units = ROWS*25 float4 ----
    float4* outv = reinterpret_cast<float4*>(out + (size_t)blockIdx.x * ROWS * NU);
    #pragma unroll
    for (int it = 0; it < (ROWS * NU / 4) / ROWS; it++) {   // 25 iterations
        int i = tid + it * ROWS;        // linear float4 index within tile
        int r = i / 25;                 // row within tile (100/4 = 25 vec4 per row)
        int g = i - r * 25;             // vec4 group within row
        float t = sTd[r];
        float4 c  = *reinterpret_cast<const float4*>(sCum  + 4 * g);
        float4 pm = *reinterpret_cast<const float4*>(sPmax + 4 * g);
        float4 p;
        p.x = fminf(fmaxf(t - c.x, 0.0f), pm.x);
        p.y = fminf(fmaxf(t - c.y, 0.0f), pm.y);
        p.z = fminf(fmaxf(t - c.z, 0.0f), pm.z);
        p.w = fminf(fmaxf(t - c.w, 0.0f), pm.w);
        outv[i] = p;
    }
}

// ---------------------------------------------------------------------------
// Launch
// Input order (metadata): x, Cost, Pmax, Pd, w_capacity, W1, b1, W2, b2, W3, b3
// ---------------------------------------------------------------------------
extern "C" void kernel_launch(void* const* d_in, const int* in_sizes, int n_in,
                              void* d_out, int out_size) {
    const float* x     = (const float*)d_in[0];
    const float* Cost  = (const float*)d_in[1];
    const float* Pmax  = (const float*)d_in[2];
    const float* Pd    = (const float*)d_in[3];
    const float* wcap  = (const float*)d_in[4];
    const float* W1    = (const float*)d_in[5];
    const float* b1    = (const float*)d_in[6];
    const float* W2    = (const float*)d_in[7];
    const float* b2    = (const float*)d_in[8];
    const float* W3    = (const float*)d_in[9];
    const float* b3    = (const float*)d_in[10];
    float* out = (float*)d_out;

    const int B = in_sizes[0] / 4;      // x is [B, 4]

    setup_kernel<<<1, 128>>>(Cost, Pmax, Pd);

    const int blocks = B / ROWS;        // 262144 / 256 = 1024
    mlp_dispatch_kernel<<<blocks, ROWS>>>(
        (const float4*)x, W1, b1, W2, b2, W3, b3, Pmax, wcap, out);
}

// round 4
// speedup vs baseline: 1.3516x; 1.3516x over previous
#include <cuda_runtime.h>
#include <cuda_bf16.h>

// Problem constants: IN=4, H=30, OUT=1, N_UNIT=100, B=262144
#define NU    100
#define HH    30
#define NT    256          // threads per block
#define RPT   2            // rows per thread
#define RPB   (NT * RPT)   // 512 rows per block

typedef unsigned long long u64;

// ---- packed f32x2 helpers (sm_103a) ----
__device__ __forceinline__ u64 ffma2(u64 a, u64 b, u64 c) {
    u64 d;
    asm("fma.rn.f32x2 %0, %1, %2, %3;" : "=l"(d) : "l"(a), "l"(b), "l"(c));
    return d;
}
__device__ __forceinline__ u64 pack2(float x, float y) {
    u64 d;
    asm("mov.b64 %0, {%1, %2};" : "=l"(d) : "f"(x), "f"(y));
    return d;
}
__device__ __forceinline__ float2 unpack2(u64 a) {
    float2 f;
    asm("mov.b64 {%0, %1}, %2;" : "=f"(f.x), "=f"(f.y) : "l"(a));
    return f;
}
__device__ __forceinline__ u64 relu2(u64 a) {
    float2 f = unpack2(a);
    return pack2(fmaxf(f.x, 0.0f), fmaxf(f.y, 0.0f));
}

// Scratch from setup kernel (no allocations allowed)
__device__ float g_cum[NU];    // exclusive cum. Pmax of cheaper units, per ORIGINAL index
__device__ float g_sumPd;      // sum(Pd)

// ---------------------------------------------------------------------------
// Setup: stable argsort(Cost) merit order, closed form per original unit.
// ---------------------------------------------------------------------------
__global__ void setup_kernel(const float* __restrict__ Cost,
                             const float* __restrict__ Pmax,
                             const float* __restrict__ Pd) {
    __shared__ float sc[NU], sp[NU];
    int j = threadIdx.x;
    if (j < NU) { sc[j] = Cost[j]; sp[j] = Pmax[j]; }
    __syncthreads();
    if (j < NU) {
        float cj = sc[j];
        float cum = 0.0f;
        #pragma unroll 4
        for (int k = 0; k < NU; k++) {
            float ck = sc[k];
            bool cheaper = (ck < cj) || (ck == cj && k < j);
            if (cheaper) cum += sp[k];
        }
        g_cum[j] = cum;
    }
    if (j == 0) {
        float s = 0.0f;
        for (int k = 0; k < NU; k++) s += Pd[k];
        g_sumPd = s;
    }
}

// ---------------------------------------------------------------------------
// Main: 2 rows/thread, packed f32x2 MLP, coalesced float4 tile stores.
// ---------------------------------------------------------------------------
__global__ __launch_bounds__(NT, 2)
void mlp_dispatch_kernel(const float4* __restrict__ x,     // [B,4] as float4
                         const float*  __restrict__ W1,    // [4,30]
                         const float*  __restrict__ b1,    // [30]
                         const float*  __restrict__ W2,    // [30,30]
                         const float*  __restrict__ b2,    // [30]
                         const float*  __restrict__ W3,    // [30,1]
                         const float*  __restrict__ b3,    // [1]
                         const float*  __restrict__ Pmax,  // [100]
                         const float*  __restrict__ wcap,  // [1]
                         float*        __restrict__ out)   // [B,100]
{
    // duplicated-weight shared arrays: element i holds (w_i, w_i)
    __shared__ alignas(16) u64 sW1d[4 * HH];
    __shared__ alignas(16) u64 sW2d[HH * HH];
    __shared__ alignas(16) u64 sb1d[HH];
    __shared__ alignas(16) u64 sb2d[HH];
    __shared__ alignas(16) u64 sW3d[HH];
    __shared__ alignas(16) float sCum[NU];
    __shared__ alignas(16) float sPmax[NU];
    __shared__ alignas(16) float sTd[RPB];
    __shared__ float sB3, sWc, sSum;

    const int tid = threadIdx.x;

    // Stage params (duplicate into both f32x2 lanes)
    for (int i = tid; i < 4 * HH; i += NT)  { float w = W1[i]; sW1d[i] = pack2(w, w); }
    for (int i = tid; i < HH * HH; i += NT) { float w = W2[i]; sW2d[i] = pack2(w, w); }
    if (tid < HH) {
        float v1 = b1[tid]; sb1d[tid] = pack2(v1, v1);
        float v2 = b2[tid]; sb2d[tid] = pack2(v2, v2);
        float v3 = W3[tid]; sW3d[tid] = pack2(v3, v3);
    }
    if (tid < NU) { sCum[tid] = g_cum[tid]; sPmax[tid] = Pmax[tid]; }
    if (tid == 0) { sB3 = b3[0]; sWc = wcap[0]; sSum = g_sumPd; }
    __syncthreads();

    // ---- load this thread's 2 rows of x and transpose into packed lanes ----
    const long row0 = ((long)blockIdx.x * NT + tid) * RPT;
    const float4 x0 = x[row0];
    const float4 x1 = x[row0 + 1];
    const u64 xp0 = pack2(x0.x, x1.x);
    const u64 xp1 = pack2(x0.y, x1.y);
    const u64 xp2 = pack2(x0.z, x1.z);
    const u64 xp3 = pack2(x0.w, x1.w);

    // ---- layer 2 accumulators (packed pair per hidden unit) ----
    u64 h2p[HH];
    #pragma unroll
    for (int k = 0; k < HH; k++) h2p[k] = sb2d[k];

    // ---- h1 in chunks of 10 to bound live registers ----
    #pragma unroll
    for (int c = 0; c < 3; c++) {
        u64 h1p[10];
        #pragma unroll
        for (int ii = 0; ii < 10; ii++) {
            const int i = c * 10 + ii;
            u64 a = sb1d[i];
            a = ffma2(xp0, sW1d[0 * HH + i], a);
            a = ffma2(xp1, sW1d[1 * HH + i], a);
            a = ffma2(xp2, sW1d[2 * HH + i], a);
            a = ffma2(xp3, sW1d[3 * HH + i], a);
            h1p[ii] = relu2(a);
        }
        #pragma unroll
        for (int ii = 0; ii < 10; ii++) {
            const int i = c * 10 + ii;
            const u64 h = h1p[ii];
            // pairwise LDS.128 over k (i*HH + k is even when k is even -> 16B aligned)
            #pragma unroll
            for (int k = 0; k < HH; k += 2) {
                ulonglong2 w = *reinterpret_cast<const ulonglong2*>(&sW2d[i * HH + k]);
                h2p[k]     = ffma2(h, w.x, h2p[k]);
                h2p[k + 1] = ffma2(h, w.y, h2p[k + 1]);
            }
        }
    }

    // ---- output layer: y = relu(h2) . W3 + b3 (packed) ----
    u64 yp = pack2(sB3, sB3);
    #pragma unroll
    for (int i = 0; i < HH; i++)
        yp = ffma2(relu2(h2p[i]), sW3d[i], yp);
    const float2 yv = unpack2(yp);

    sTd[tid * RPT]     = sSum - sWc * yv.x;
    sTd[tid * RPT + 1] = sSum - sWc * yv.y;
    __syncthreads();

    // ---- coalesced tile store: RPB rows x 100 units = RPB*25 float4 ----
    float4* outv = reinterpret_cast<float4*>(out + (size_t)blockIdx.x * RPB * NU);
    #pragma unroll
    for (int it = 0; it < (RPB * NU / 4) / NT; it++) {   // 50 iterations
        int i = tid + it * NT;          // linear float4 index within tile
        int r = i / 25;                 // row within tile (25 vec4 per row)
        int g = i - r * 25;             // vec4 group within row
        float t = sTd[r];
        float4 cu = *reinterpret_cast<const float4*>(sCum  + 4 * g);
        float4 pm = *reinterpret_cast<const float4*>(sPmax + 4 * g);
        float4 p;
        p.x = fminf(fmaxf(t - cu.x, 0.0f), pm.x);
        p.y = fminf(fmaxf(t - cu.y, 0.0f), pm.y);
        p.z = fminf(fmaxf(t - cu.z, 0.0f), pm.z);
        p.w = fminf(fmaxf(t - cu.w, 0.0f), pm.w);
        outv[i] = p;
    }
}

// ---------------------------------------------------------------------------
// Launch. Input order: x, Cost, Pmax, Pd, w_capacity, W1, b1, W2, b2, W3, b3
// ---------------------------------------------------------------------------
extern "C" void kernel_launch(void* const* d_in, const int* in_sizes, int n_in,
                              void* d_out, int out_size) {
    const float* x     = (const float*)d_in[0];
    const float* Cost  = (const float*)d_in[1];
    const float* Pmax  = (const float*)d_in[2];
    const float* Pd    = (const float*)d_in[3];
    const float* wcap  = (const float*)d_in[4];
    const float* W1    = (const float*)d_in[5];
    const float* b1    = (const float*)d_in[6];
    const float* W2    = (const float*)d_in[7];
    const float* b2    = (const float*)d_in[8];
    const float* W3    = (const float*)d_in[9];
    const float* b3    = (const float*)d_in[10];
    float* out = (float*)d_out;

    const int B = in_sizes[0] / 4;      // x is [B, 4]

    setup_kernel<<<1, 128>>>(Cost, Pmax, Pd);

    const int blocks = B / RPB;         // 262144 / 512 = 512
    mlp_dispatch_kernel<<<blocks, NT>>>(
        (const float4*)x, W1, b1, W2, b2, W3, b3, Pmax, wcap, out);
}